// round 1
// baseline (speedup 1.0000x reference)
#include <cuda_runtime.h>
#include <cuda_bf16.h>
#include <math.h>

// Problem constants
#define BSZ 4
#define SEQ 1024
#define DMODEL 1024
#define NHEAD 16
#define DHEAD 64
#define LPE 2045   // 2*s-1, s = 1023

// Scratch (static __device__ allocations; no cudaMalloc allowed)
__device__ float g_qkv[BSZ * SEQ * 3 * DMODEL];   // (4096, 3072)
__device__ float g_pe [LPE * DMODEL];              // (2045, 1024)
__device__ float g_pek[LPE * DMODEL];              // (2045, 1024) = pe @ W_pe
__device__ float g_ao [BSZ * SEQ * DMODEL];        // attention output (b,S,d)

// ---------------------------------------------------------------------------
// Sinusoidal positional embedding generator: pe[l, kk]
//   t = l - 1022; denom = 10000^(2*(kk/2)/1024)
//   even kk -> sin(t/denom), odd -> cos(t/denom); scaled by d^-0.5 = 1/32
// ---------------------------------------------------------------------------
__global__ void pegen_kernel(float* __restrict__ pe) {
    int idx = blockIdx.x * blockDim.x + threadIdx.x;
    if (idx >= LPE * DMODEL) return;
    int l  = idx >> 10;
    int kk = idx & 1023;
    int p2 = kk & ~1;
    float expnt = (float)p2 / 1024.0f;
    float denom = powf(10000.0f, expnt);
    float t = (float)(l - 1022);
    float ang = t / denom;
    float v = (kk & 1) ? cosf(ang) : sinf(ang);
    pe[idx] = v * 0.03125f;
}

// ---------------------------------------------------------------------------
// Tiled SGEMM: C[M,N] = A[M,K] @ B[K,N], row-major fp32.
// BM=128, BN=128, BK=8, 256 threads, 8x8 micro-tile per thread.
// Guards on M only (K multiple of 8, N multiple of 128 for all our calls).
// ---------------------------------------------------------------------------
#define GBM 128
#define GBN 128
#define GBK 8

__global__ __launch_bounds__(256)
void sgemm_kernel(const float* __restrict__ A, const float* __restrict__ B,
                  float* __restrict__ C, int M, int N, int K) {
    __shared__ float As[GBK][GBM + 4];  // transposed A tile, padded
    __shared__ float Bs[GBK][GBN];

    int tid = threadIdx.x;
    int bm = blockIdx.y * GBM;
    int bn = blockIdx.x * GBN;

    int arow = tid >> 1;            // 0..127
    int acol = (tid & 1) * 4;       // 0 or 4
    int brow = tid >> 5;            // 0..7
    int bcol = (tid & 31) * 4;      // 0..124

    int tr = (tid >> 4) * 8;        // 0..120
    int tc = (tid & 15) * 8;        // 0..120

    float acc[8][8];
#pragma unroll
    for (int i = 0; i < 8; i++)
#pragma unroll
        for (int j = 0; j < 8; j++) acc[i][j] = 0.0f;

    for (int k0 = 0; k0 < K; k0 += GBK) {
        // Load A tile (transposed into smem)
        int grow = bm + arow;
        float4 av;
        if (grow < M)
            av = *(const float4*)(A + (size_t)grow * K + k0 + acol);
        else
            av = make_float4(0.f, 0.f, 0.f, 0.f);
        As[acol + 0][arow] = av.x;
        As[acol + 1][arow] = av.y;
        As[acol + 2][arow] = av.z;
        As[acol + 3][arow] = av.w;
        // Load B tile
        float4 bv = *(const float4*)(B + (size_t)(k0 + brow) * N + bn + bcol);
        *(float4*)(&Bs[brow][bcol]) = bv;
        __syncthreads();

#pragma unroll
        for (int k = 0; k < GBK; k++) {
            float af[8], bf[8];
            *(float4*)(af)     = *(const float4*)(&As[k][tr]);
            *(float4*)(af + 4) = *(const float4*)(&As[k][tr + 4]);
            *(float4*)(bf)     = *(const float4*)(&Bs[k][tc]);
            *(float4*)(bf + 4) = *(const float4*)(&Bs[k][tc + 4]);
#pragma unroll
            for (int i = 0; i < 8; i++)
#pragma unroll
                for (int j = 0; j < 8; j++)
                    acc[i][j] = fmaf(af[i], bf[j], acc[i][j]);
        }
        __syncthreads();
    }

    // Store
#pragma unroll
    for (int i = 0; i < 8; i++) {
        int grow = bm + tr + i;
        if (grow < M) {
            float4 v0 = make_float4(acc[i][0], acc[i][1], acc[i][2], acc[i][3]);
            float4 v1 = make_float4(acc[i][4], acc[i][5], acc[i][6], acc[i][7]);
            *(float4*)(C + (size_t)grow * N + bn + tc)     = v0;
            *(float4*)(C + (size_t)grow * N + bn + tc + 4) = v1;
        }
    }
}

// ---------------------------------------------------------------------------
// Fused relative-position attention (flash style, fp32).
// Grid: blockIdx.x = (b*16 + h)*16 + qtile.  256 threads.
// Per block: 64 queries x all 1024 keys, dh = 64.
//
// logits[qi,kj] = (q_c[qi].k[kj] + [qi>=1 && kj>=1] * q_p[qi].pe_key[1022+kj-qi]) * 0.125
//                 + mask[kj]
// q_c = q + content_bias; q_p = q + pos_bias (zeroed for qi==0).
// pe band per (qtile,ktile) is 127 rows, staged transposed in smem.
// ---------------------------------------------------------------------------
// smem layout in floats:
#define OFF_QCT 0            // [64][65] c-major
#define OFF_QPT 4160         // [64][65]
#define OFF_KT  8320         // [64][65]
#define OFF_VS  12480        // [64][64] natural (j-major)
#define OFF_PET 16576        // [64][129] c-major, band idx 0..126
#define OFF_PT  24832        // [64][65] j-major (P^T: [j][i])
#define OFF_MSK 28992        // [64]
#define SMEM_FLOATS 29056
#define SMEM_BYTES (SMEM_FLOATS * 4)

__global__ __launch_bounds__(256, 1)
void attn_kernel(const float* __restrict__ qkv, const float* __restrict__ pek,
                 const unsigned char* __restrict__ mask,
                 const float* __restrict__ cb, const float* __restrict__ pb,
                 float* __restrict__ ao) {
    extern __shared__ float sm[];
    float* Qct = sm + OFF_QCT;
    float* Qpt = sm + OFF_QPT;
    float* Kt  = sm + OFF_KT;
    float* Vs  = sm + OFF_VS;
    float* PEt = sm + OFF_PET;
    float* Pt  = sm + OFF_PT;
    float* Msk = sm + OFF_MSK;

    int tid = threadIdx.x;
    int qt = blockIdx.x & 15;
    int bh = blockIdx.x >> 4;
    int h  = bh & 15;
    int b  = bh >> 4;
    int q0 = qt * 64;

    const float* cbh = cb + h * DHEAD;
    const float* pbh = pb + h * DHEAD;

    // Load Q tile (content and pos variants), transposed
    for (int idx = tid; idx < 64 * 64; idx += 256) {
        int i = idx >> 6, c = idx & 63;
        int qi = q0 + i;
        float v = qkv[((size_t)(b * SEQ + qi)) * 3072 + h * 192 + c];
        Qct[c * 65 + i] = v + cbh[c];
        Qpt[c * 65 + i] = (qi == 0) ? 0.0f : (v + pbh[c]);
    }

    int ty = tid >> 4, tx = tid & 15;
    int ib = ty * 4, jb = tx * 4;
    int db = jb - ib + 63;  // band index base (3..123)

    float o[4][4];
    float mrow[4], lrow[4];
#pragma unroll
    for (int a = 0; a < 4; a++) {
        mrow[a] = -1e30f;
        lrow[a] = 0.0f;
#pragma unroll
        for (int c = 0; c < 4; c++) o[a][c] = 0.0f;
    }

    for (int k0 = 0; k0 < SEQ; k0 += 64) {
        __syncthreads();  // protect smem reuse (and first-iter Q visibility)
        // Load K (transposed) and V (natural)
        for (int idx = tid; idx < 64 * 64; idx += 256) {
            int j = idx >> 6, c = idx & 63;
            size_t base = ((size_t)(b * SEQ + k0 + j)) * 3072 + h * 192;
            Kt[c * 65 + j] = qkv[base + 64 + c];
            Vs[j * 64 + c] = qkv[base + 128 + c];
        }
        // Load PE band: band idx bi in [0,127), row l = 959 + k0 - q0 + bi
        int lbase = 959 + k0 - q0;
        for (int idx = tid; idx < 127 * 64; idx += 256) {
            int bi = idx >> 6, c = idx & 63;
            int l = lbase + bi;
            float v = (l >= 0 && l < LPE)
                          ? pek[(size_t)l * DMODEL + h * DHEAD + c] : 0.0f;
            PEt[c * 129 + bi] = v;
        }
        if (tid < 64) Msk[tid] = mask[b * SEQ + k0 + tid] ? -1e30f : 0.0f;
        __syncthreads();

        // Scores: content + pos accumulators
        float aC[4][4], aP[4][4];
#pragma unroll
        for (int a = 0; a < 4; a++)
#pragma unroll
            for (int bb = 0; bb < 4; bb++) { aC[a][bb] = 0.f; aP[a][bb] = 0.f; }

#pragma unroll 8
        for (int c = 0; c < 64; c++) {
            float qc[4], qp[4], kk[4], pe7[7];
#pragma unroll
            for (int a = 0; a < 4; a++) {
                qc[a] = Qct[c * 65 + ib + a];
                qp[a] = Qpt[c * 65 + ib + a];
                kk[a] = Kt[c * 65 + jb + a];
            }
#pragma unroll
            for (int t = 0; t < 7; t++) pe7[t] = PEt[c * 129 + db - 3 + t];
#pragma unroll
            for (int a = 0; a < 4; a++)
#pragma unroll
                for (int bb = 0; bb < 4; bb++) {
                    aC[a][bb] = fmaf(qc[a], kk[bb], aC[a][bb]);
                    aP[a][bb] = fmaf(qp[a], pe7[bb - a + 3], aP[a][bb]);
                }
        }

        // Combine, mask, tile row-max
        float p[4][4], mt[4];
#pragma unroll
        for (int a = 0; a < 4; a++) {
            mt[a] = -1e30f;
#pragma unroll
            for (int bb = 0; bb < 4; bb++) {
                float pos = aP[a][bb];
                if (k0 + jb + bb == 0) pos = 0.0f;   // kj==0: no pos term
                float sc = (aC[a][bb] + pos) * 0.125f + Msk[jb + bb];
                p[a][bb] = sc;
                mt[a] = fmaxf(mt[a], sc);
            }
        }
        // Reduce max over the 16-lane row group
#pragma unroll
        for (int off = 1; off < 16; off <<= 1)
#pragma unroll
            for (int a = 0; a < 4; a++)
                mt[a] = fmaxf(mt[a], __shfl_xor_sync(0xffffffffu, mt[a], off, 16));

        // Online softmax update
        float rs[4];
#pragma unroll
        for (int a = 0; a < 4; a++) {
            float mn = fmaxf(mrow[a], mt[a]);
            float corr = __expf(mrow[a] - mn);
            mrow[a] = mn;
            lrow[a] *= corr;
#pragma unroll
            for (int bb = 0; bb < 4; bb++) o[a][bb] *= corr;
            float sum = 0.0f;
#pragma unroll
            for (int bb = 0; bb < 4; bb++) {
                float e = __expf(p[a][bb] - mn);
                p[a][bb] = e;
                sum += e;
            }
            rs[a] = sum;
        }
#pragma unroll
        for (int off = 1; off < 16; off <<= 1)
#pragma unroll
            for (int a = 0; a < 4; a++)
                rs[a] += __shfl_xor_sync(0xffffffffu, rs[a], off, 16);
#pragma unroll
        for (int a = 0; a < 4; a++) lrow[a] += rs[a];

        // Write P^T to smem
#pragma unroll
        for (int a = 0; a < 4; a++)
#pragma unroll
            for (int bb = 0; bb < 4; bb++)
                Pt[(jb + bb) * 65 + ib + a] = p[a][bb];
        __syncthreads();

        // o += P @ V   (thread owns rows ib.., cols jb.. of output)
#pragma unroll 4
        for (int j = 0; j < 64; j++) {
            float pv[4], vv[4];
#pragma unroll
            for (int a = 0; a < 4; a++) pv[a] = Pt[j * 65 + ib + a];
#pragma unroll
            for (int bb = 0; bb < 4; bb++) vv[bb] = Vs[j * 64 + jb + bb];
#pragma unroll
            for (int a = 0; a < 4; a++)
#pragma unroll
                for (int bb = 0; bb < 4; bb++)
                    o[a][bb] = fmaf(pv[a], vv[bb], o[a][bb]);
        }
    }

    // Normalize and write attention output as (b, S, nh*dh)
#pragma unroll
    for (int a = 0; a < 4; a++) {
        float inv = 1.0f / lrow[a];
#pragma unroll
        for (int bb = 0; bb < 4; bb++)
            ao[((size_t)(b * SEQ + q0 + ib + a)) * DMODEL + h * DHEAD + jb + bb]
                = o[a][bb] * inv;
    }
}

// ---------------------------------------------------------------------------
// Launch
// Inputs (metadata order): x, src_mask, W_qkv, W_pe, W_o, content_bias, pos_bias
// ---------------------------------------------------------------------------
extern "C" void kernel_launch(void* const* d_in, const int* in_sizes, int n_in,
                              void* d_out, int out_size) {
    const float* x          = (const float*)d_in[0];
    const unsigned char* mk = (const unsigned char*)d_in[1];
    const float* Wqkv       = (const float*)d_in[2];
    const float* Wpe        = (const float*)d_in[3];
    const float* Wo         = (const float*)d_in[4];
    const float* cb         = (const float*)d_in[5];
    const float* pb         = (const float*)d_in[6];
    float* out              = (float*)d_out;

    float *qkv, *pe, *pek, *ao;
    cudaGetSymbolAddress((void**)&qkv, g_qkv);
    cudaGetSymbolAddress((void**)&pe,  g_pe);
    cudaGetSymbolAddress((void**)&pek, g_pek);
    cudaGetSymbolAddress((void**)&ao,  g_ao);

    // 1. positional embedding table
    pegen_kernel<<<(LPE * DMODEL + 255) / 256, 256>>>(pe);

    // 2. qkv = x @ W_qkv   (4096 x 3072 x 1024)
    {
        dim3 grid(3072 / GBN, 4096 / GBM);
        sgemm_kernel<<<grid, 256>>>(x, Wqkv, qkv, BSZ * SEQ, 3 * DMODEL, DMODEL);
    }

    // 3. pe_key = pe @ W_pe   (2045 x 1024 x 1024)
    {
        dim3 grid(1024 / GBN, (LPE + GBM - 1) / GBM);
        sgemm_kernel<<<grid, 256>>>(pe, Wpe, pek, LPE, DMODEL, DMODEL);
    }

    // 4. fused attention
    cudaFuncSetAttribute(attn_kernel, cudaFuncAttributeMaxDynamicSharedMemorySize,
                         SMEM_BYTES);
    attn_kernel<<<BSZ * NHEAD * (SEQ / 64), 256, SMEM_BYTES>>>(qkv, pek, mk, cb, pb, ao);

    // 5. out = ao @ W_o   (4096 x 1024 x 1024)
    {
        dim3 grid(1024 / GBN, 4096 / GBM);
        sgemm_kernel<<<grid, 256>>>(ao, Wo, out, BSZ * SEQ, DMODEL, DMODEL);
    }
}

// round 3
// speedup vs baseline: 1.4028x; 1.4028x over previous
#include <cuda_runtime.h>
#include <cuda_bf16.h>
#include <cstdint>
#include <math.h>

// Problem constants
#define BSZ 4
#define SEQ 1024
#define DMODEL 1024
#define NHEAD 16
#define DHEAD 64
#define LPE 2045   // 2*s-1, s = 1023

// Scratch (static __device__ allocations; no cudaMalloc allowed)
__device__ float g_qkv[BSZ * SEQ * 3 * DMODEL];   // (4096, 3072)
__device__ float g_pe [LPE * DMODEL];              // (2045, 1024)
__device__ float g_pek[LPE * DMODEL];              // (2045, 1024) = pe @ W_pe
__device__ float g_ao [BSZ * SEQ * DMODEL];        // attention output (b,S,d)

// ---------------------------------------------------------------------------
// Helpers
// ---------------------------------------------------------------------------
__device__ __forceinline__ uint32_t f2tf32(float x) {
    uint32_t y;
    asm("cvt.rna.tf32.f32 %0, %1;" : "=r"(y) : "f"(x));
    return y;
}

// m16n8k8 tf32 mma (baseline PTX, sm_80+; runs on sm_103a tensor pipe)
__device__ __forceinline__ void mma_tf32(float* d, const uint32_t* a,
                                         const uint32_t* b) {
    asm volatile(
        "mma.sync.aligned.m16n8k8.row.col.f32.tf32.tf32.f32 "
        "{%0,%1,%2,%3}, {%4,%5,%6,%7}, {%8,%9}, {%0,%1,%2,%3};\n"
        : "+f"(d[0]), "+f"(d[1]), "+f"(d[2]), "+f"(d[3])
        : "r"(a[0]), "r"(a[1]), "r"(a[2]), "r"(a[3]),
          "r"(b[0]), "r"(b[1]));
}

// ---------------------------------------------------------------------------
// Sinusoidal positional embedding generator
// ---------------------------------------------------------------------------
__global__ void pegen_kernel(float* __restrict__ pe) {
    int idx = blockIdx.x * blockDim.x + threadIdx.x;
    if (idx >= LPE * DMODEL) return;
    int l  = idx >> 10;
    int kk = idx & 1023;
    int p2 = kk & ~1;
    float expnt = (float)p2 / 1024.0f;
    float denom = powf(10000.0f, expnt);
    float t = (float)(l - 1022);
    float ang = t / denom;
    float v = (kk & 1) ? cosf(ang) : sinf(ang);
    pe[idx] = v * 0.03125f;
}

// ===========================================================================
// TF32 mma.sync GEMM: C[M,N] = A[M,K] @ B[K,N], row-major fp32.
// BM=128, BN=128, BK=32.  256 threads = 8 warps in 2(m) x 4(n), warp tile
// 64x32, micro: m16n8k8 tf32.  Double-buffered smem, reg-prefetch pipeline.
// Requirements: N % 128 == 0, K % 32 == 0 (true for all calls); M guarded.
//
// Smem layouts (floats):
//   As[2][128][ASTR=36]: frag load bank = (4*g + tg) % 32 -> conflict-free
//   Bs[2][32][BSTR=136]: frag load bank = (8*tg + g) % 32 -> conflict-free
// ===========================================================================
#define ASTR 36
#define BSTR 136
#define A_STAGE (128 * ASTR)
#define B_STAGE (32 * BSTR)
#define GEMM_SMEM_BYTES ((2 * A_STAGE + 2 * B_STAGE) * 4)

__global__ __launch_bounds__(256)
void gemm_mma_kernel(const float* __restrict__ A, const float* __restrict__ B,
                     float* __restrict__ C, int M, int N, int K) {
    extern __shared__ float sm[];
    float* AsBase = sm;                    // [2][128][ASTR]
    float* BsBase = sm + 2 * A_STAGE;      // [2][32][BSTR]

    int tid  = threadIdx.x;
    int wid  = tid >> 5;
    int lane = tid & 31;
    int g    = lane >> 2;       // group id (0..7)
    int tg   = lane & 3;        // thread-in-group (0..3)
    int wm0  = (wid >> 2) * 64; // warp m origin within CTA tile
    int wn0  = (wid & 3) * 32;  // warp n origin
    int bm = blockIdx.y * 128;
    int bn = blockIdx.x * 128;

    float acc[4][4][4];
#pragma unroll
    for (int mt = 0; mt < 4; mt++)
#pragma unroll
        for (int nt = 0; nt < 4; nt++)
#pragma unroll
            for (int r = 0; r < 4; r++) acc[mt][nt][r] = 0.0f;

    float4 pa[4], pb[4];

    auto ldTile = [&](int k0) {
#pragma unroll
        for (int it = 0; it < 4; it++) {
            int l = tid + 256 * it;
            int row = l >> 3, c4 = (l & 7) << 2;
            int gr = bm + row;
            pa[it] = (gr < M)
                ? *(const float4*)(A + (size_t)gr * K + k0 + c4)
                : make_float4(0.f, 0.f, 0.f, 0.f);
        }
#pragma unroll
        for (int it = 0; it < 4; it++) {
            int l = tid + 256 * it;
            int kr = l >> 5, n4 = (l & 31) << 2;
            pb[it] = *(const float4*)(B + (size_t)(k0 + kr) * N + bn + n4);
        }
    };

    auto stsTile = [&](int s) {
        float* as = AsBase + s * A_STAGE;
        float* bs = BsBase + s * B_STAGE;
#pragma unroll
        for (int it = 0; it < 4; it++) {
            int l = tid + 256 * it;
            int row = l >> 3, c4 = (l & 7) << 2;
            uint4 v = make_uint4(f2tf32(pa[it].x), f2tf32(pa[it].y),
                                 f2tf32(pa[it].z), f2tf32(pa[it].w));
            *(uint4*)(as + row * ASTR + c4) = v;
        }
#pragma unroll
        for (int it = 0; it < 4; it++) {
            int l = tid + 256 * it;
            int kr = l >> 5, n4 = (l & 31) << 2;
            uint4 v = make_uint4(f2tf32(pb[it].x), f2tf32(pb[it].y),
                                 f2tf32(pb[it].z), f2tf32(pb[it].w));
            *(uint4*)(bs + kr * BSTR + n4) = v;
        }
    };

    auto compute = [&](int s) {
        const float* as = AsBase + s * A_STAGE;
        const float* bs = BsBase + s * B_STAGE;
#pragma unroll
        for (int ks = 0; ks < 4; ks++) {
            int k8 = ks * 8;
            uint32_t af[4][4], bf[4][2];
#pragma unroll
            for (int mt = 0; mt < 4; mt++) {
                const float* p = as + (wm0 + mt * 16 + g) * ASTR + k8 + tg;
                af[mt][0] = __float_as_uint(p[0]);
                af[mt][1] = __float_as_uint(p[8 * ASTR]);
                af[mt][2] = __float_as_uint(p[4]);
                af[mt][3] = __float_as_uint(p[8 * ASTR + 4]);
            }
#pragma unroll
            for (int nt = 0; nt < 4; nt++) {
                const float* p = bs + (k8 + tg) * BSTR + wn0 + nt * 8 + g;
                bf[nt][0] = __float_as_uint(p[0]);
                bf[nt][1] = __float_as_uint(p[4 * BSTR]);
            }
#pragma unroll
            for (int mt = 0; mt < 4; mt++)
#pragma unroll
                for (int nt = 0; nt < 4; nt++)
                    mma_tf32(acc[mt][nt], af[mt], bf[nt]);
        }
    };

    int T = K >> 5;
    // Prologue
    ldTile(0);
    stsTile(0);
    __syncthreads();

    for (int t = 0; t < T; t++) {
        int s = t & 1;
        if (t + 1 < T) ldTile((t + 1) << 5);
        compute(s);
        if (t + 1 < T) {
            stsTile(s ^ 1);
            __syncthreads();
        }
    }

    // Epilogue: c0,c1 -> (row g, cols 2tg,2tg+1); c2,c3 -> row g+8
#pragma unroll
    for (int mt = 0; mt < 4; mt++) {
        int r0 = bm + wm0 + mt * 16 + g;
        int r1 = r0 + 8;
#pragma unroll
        for (int nt = 0; nt < 4; nt++) {
            int col = bn + wn0 + nt * 8 + 2 * tg;
            if (r0 < M)
                *(float2*)(C + (size_t)r0 * N + col) =
                    make_float2(acc[mt][nt][0], acc[mt][nt][1]);
            if (r1 < M)
                *(float2*)(C + (size_t)r1 * N + col) =
                    make_float2(acc[mt][nt][2], acc[mt][nt][3]);
        }
    }
}

// ---------------------------------------------------------------------------
// Fused relative-position attention (flash style, fp32).  UNCHANGED from R1.
// ---------------------------------------------------------------------------
#define OFF_QCT 0            // [64][65] c-major
#define OFF_QPT 4160         // [64][65]
#define OFF_KT  8320         // [64][65]
#define OFF_VS  12480        // [64][64] natural (j-major)
#define OFF_PET 16576        // [64][129] c-major, band idx 0..126
#define OFF_PT  24832        // [64][65] j-major (P^T: [j][i])
#define OFF_MSK 28992        // [64]
#define SMEM_FLOATS 29056
#define SMEM_BYTES (SMEM_FLOATS * 4)

__global__ __launch_bounds__(256, 1)
void attn_kernel(const float* __restrict__ qkv, const float* __restrict__ pek,
                 const unsigned char* __restrict__ mask,
                 const float* __restrict__ cb, const float* __restrict__ pb,
                 float* __restrict__ ao) {
    extern __shared__ float sm[];
    float* Qct = sm + OFF_QCT;
    float* Qpt = sm + OFF_QPT;
    float* Kt  = sm + OFF_KT;
    float* Vs  = sm + OFF_VS;
    float* PEt = sm + OFF_PET;
    float* Pt  = sm + OFF_PT;
    float* Msk = sm + OFF_MSK;

    int tid = threadIdx.x;
    int qt = blockIdx.x & 15;
    int bh = blockIdx.x >> 4;
    int h  = bh & 15;
    int b  = bh >> 4;
    int q0 = qt * 64;

    const float* cbh = cb + h * DHEAD;
    const float* pbh = pb + h * DHEAD;

    for (int idx = tid; idx < 64 * 64; idx += 256) {
        int i = idx >> 6, c = idx & 63;
        int qi = q0 + i;
        float v = qkv[((size_t)(b * SEQ + qi)) * 3072 + h * 192 + c];
        Qct[c * 65 + i] = v + cbh[c];
        Qpt[c * 65 + i] = (qi == 0) ? 0.0f : (v + pbh[c]);
    }

    int ty = tid >> 4, tx = tid & 15;
    int ib = ty * 4, jb = tx * 4;
    int db = jb - ib + 63;

    float o[4][4];
    float mrow[4], lrow[4];
#pragma unroll
    for (int a = 0; a < 4; a++) {
        mrow[a] = -1e30f;
        lrow[a] = 0.0f;
#pragma unroll
        for (int c = 0; c < 4; c++) o[a][c] = 0.0f;
    }

    for (int k0 = 0; k0 < SEQ; k0 += 64) {
        __syncthreads();
        for (int idx = tid; idx < 64 * 64; idx += 256) {
            int j = idx >> 6, c = idx & 63;
            size_t base = ((size_t)(b * SEQ + k0 + j)) * 3072 + h * 192;
            Kt[c * 65 + j] = qkv[base + 64 + c];
            Vs[j * 64 + c] = qkv[base + 128 + c];
        }
        int lbase = 959 + k0 - q0;
        for (int idx = tid; idx < 127 * 64; idx += 256) {
            int bi = idx >> 6, c = idx & 63;
            int l = lbase + bi;
            float v = (l >= 0 && l < LPE)
                          ? pek[(size_t)l * DMODEL + h * DHEAD + c] : 0.0f;
            PEt[c * 129 + bi] = v;
        }
        if (tid < 64) Msk[tid] = mask[b * SEQ + k0 + tid] ? -1e30f : 0.0f;
        __syncthreads();

        float aC[4][4], aP[4][4];
#pragma unroll
        for (int a = 0; a < 4; a++)
#pragma unroll
            for (int bb = 0; bb < 4; bb++) { aC[a][bb] = 0.f; aP[a][bb] = 0.f; }

#pragma unroll 8
        for (int c = 0; c < 64; c++) {
            float qc[4], qp[4], kk[4], pe7[7];
#pragma unroll
            for (int a = 0; a < 4; a++) {
                qc[a] = Qct[c * 65 + ib + a];
                qp[a] = Qpt[c * 65 + ib + a];
                kk[a] = Kt[c * 65 + jb + a];
            }
#pragma unroll
            for (int t = 0; t < 7; t++) pe7[t] = PEt[c * 129 + db - 3 + t];
#pragma unroll
            for (int a = 0; a < 4; a++)
#pragma unroll
                for (int bb = 0; bb < 4; bb++) {
                    aC[a][bb] = fmaf(qc[a], kk[bb], aC[a][bb]);
                    aP[a][bb] = fmaf(qp[a], pe7[bb - a + 3], aP[a][bb]);
                }
        }

        float p[4][4], mt[4];
#pragma unroll
        for (int a = 0; a < 4; a++) {
            mt[a] = -1e30f;
#pragma unroll
            for (int bb = 0; bb < 4; bb++) {
                float pos = aP[a][bb];
                if (k0 + jb + bb == 0) pos = 0.0f;
                float sc = (aC[a][bb] + pos) * 0.125f + Msk[jb + bb];
                p[a][bb] = sc;
                mt[a] = fmaxf(mt[a], sc);
            }
        }
#pragma unroll
        for (int off = 1; off < 16; off <<= 1)
#pragma unroll
            for (int a = 0; a < 4; a++)
                mt[a] = fmaxf(mt[a], __shfl_xor_sync(0xffffffffu, mt[a], off, 16));

        float rs[4];
#pragma unroll
        for (int a = 0; a < 4; a++) {
            float mn = fmaxf(mrow[a], mt[a]);
            float corr = __expf(mrow[a] - mn);
            mrow[a] = mn;
            lrow[a] *= corr;
#pragma unroll
            for (int bb = 0; bb < 4; bb++) o[a][bb] *= corr;
            float sum = 0.0f;
#pragma unroll
            for (int bb = 0; bb < 4; bb++) {
                float e = __expf(p[a][bb] - mn);
                p[a][bb] = e;
                sum += e;
            }
            rs[a] = sum;
        }
#pragma unroll
        for (int off = 1; off < 16; off <<= 1)
#pragma unroll
            for (int a = 0; a < 4; a++)
                rs[a] += __shfl_xor_sync(0xffffffffu, rs[a], off, 16);
#pragma unroll
        for (int a = 0; a < 4; a++) lrow[a] += rs[a];

#pragma unroll
        for (int a = 0; a < 4; a++)
#pragma unroll
            for (int bb = 0; bb < 4; bb++)
                Pt[(jb + bb) * 65 + ib + a] = p[a][bb];
        __syncthreads();

#pragma unroll 4
        for (int j = 0; j < 64; j++) {
            float pv[4], vv[4];
#pragma unroll
            for (int a = 0; a < 4; a++) pv[a] = Pt[j * 65 + ib + a];
#pragma unroll
            for (int bb = 0; bb < 4; bb++) vv[bb] = Vs[j * 64 + jb + bb];
#pragma unroll
            for (int a = 0; a < 4; a++)
#pragma unroll
                for (int bb = 0; bb < 4; bb++)
                    o[a][bb] = fmaf(pv[a], vv[bb], o[a][bb]);
        }
    }

#pragma unroll
    for (int a = 0; a < 4; a++) {
        float inv = 1.0f / lrow[a];
#pragma unroll
        for (int bb = 0; bb < 4; bb++)
            ao[((size_t)(b * SEQ + q0 + ib + a)) * DMODEL + h * DHEAD + jb + bb]
                = o[a][bb] * inv;
    }
}

// ---------------------------------------------------------------------------
// Launch
// Inputs (metadata order): x, src_mask, W_qkv, W_pe, W_o, content_bias, pos_bias
// ---------------------------------------------------------------------------
extern "C" void kernel_launch(void* const* d_in, const int* in_sizes, int n_in,
                              void* d_out, int out_size) {
    const float* x          = (const float*)d_in[0];
    const unsigned char* mk = (const unsigned char*)d_in[1];
    const float* Wqkv       = (const float*)d_in[2];
    const float* Wpe        = (const float*)d_in[3];
    const float* Wo         = (const float*)d_in[4];
    const float* cb         = (const float*)d_in[5];
    const float* pb         = (const float*)d_in[6];
    float* out              = (float*)d_out;

    float *qkv, *pe, *pek, *ao;
    cudaGetSymbolAddress((void**)&qkv, g_qkv);
    cudaGetSymbolAddress((void**)&pe,  g_pe);
    cudaGetSymbolAddress((void**)&pek, g_pek);
    cudaGetSymbolAddress((void**)&ao,  g_ao);

    cudaFuncSetAttribute(gemm_mma_kernel,
                         cudaFuncAttributeMaxDynamicSharedMemorySize,
                         GEMM_SMEM_BYTES);
    cudaFuncSetAttribute(attn_kernel, cudaFuncAttributeMaxDynamicSharedMemorySize,
                         SMEM_BYTES);

    // 1. positional embedding table
    pegen_kernel<<<(LPE * DMODEL + 255) / 256, 256>>>(pe);

    // 2. qkv = x @ W_qkv   (4096 x 3072 x 1024)
    {
        dim3 grid(3072 / 128, 4096 / 128);
        gemm_mma_kernel<<<grid, 256, GEMM_SMEM_BYTES>>>(x, Wqkv, qkv,
                                                        BSZ * SEQ, 3 * DMODEL, DMODEL);
    }

    // 3. pe_key = pe @ W_pe   (2045 x 1024 x 1024)
    {
        dim3 grid(1024 / 128, (LPE + 127) / 128);
        gemm_mma_kernel<<<grid, 256, GEMM_SMEM_BYTES>>>(pe, Wpe, pek,
                                                        LPE, DMODEL, DMODEL);
    }

    // 4. fused attention
    attn_kernel<<<BSZ * NHEAD * (SEQ / 64), 256, SMEM_BYTES>>>(qkv, pek, mk, cb, pb, ao);

    // 5. out = ao @ W_o   (4096 x 1024 x 1024)
    {
        dim3 grid(1024 / 128, 4096 / 128);
        gemm_mma_kernel<<<grid, 256, GEMM_SMEM_BYTES>>>(ao, Wo, out,
                                                        BSZ * SEQ, DMODEL, DMODEL);
    }
}

// round 4
// speedup vs baseline: 3.0946x; 2.2061x over previous
#include <cuda_runtime.h>
#include <cuda_bf16.h>
#include <cstdint>
#include <math.h>

// Problem constants
#define BSZ 4
#define SEQ 1024
#define DMODEL 1024
#define NHEAD 16
#define DHEAD 64
#define LPE 2045   // 2*s-1, s = 1023

// Scratch
__device__ float g_qkv[BSZ * SEQ * 3 * DMODEL];
__device__ float g_pe [LPE * DMODEL];
__device__ float g_pek[LPE * DMODEL];
__device__ float g_ao [BSZ * SEQ * DMODEL];

// ---------------------------------------------------------------------------
__device__ __forceinline__ uint32_t f2tf32(float x) {
    uint32_t y;
    asm("cvt.rna.tf32.f32 %0, %1;" : "=r"(y) : "f"(x));
    return y;
}
__device__ __forceinline__ float f2tf32f(float x) {
    return __uint_as_float(f2tf32(x));
}

__device__ __forceinline__ void mma_tf32(float* d, const uint32_t* a,
                                         const uint32_t* b) {
    asm volatile(
        "mma.sync.aligned.m16n8k8.row.col.f32.tf32.tf32.f32 "
        "{%0,%1,%2,%3}, {%4,%5,%6,%7}, {%8,%9}, {%0,%1,%2,%3};\n"
        : "+f"(d[0]), "+f"(d[1]), "+f"(d[2]), "+f"(d[3])
        : "r"(a[0]), "r"(a[1]), "r"(a[2]), "r"(a[3]),
          "r"(b[0]), "r"(b[1]));
}

// XOR-swizzled 64-float row layout: conflict-free frag loads + optimal STS.128
__device__ __forceinline__ int swz(int row, int col) {
    return row * 64 + ((((col >> 2) ^ (row & 7)) << 2) | (col & 3));
}

// ---------------------------------------------------------------------------
__global__ void pegen_kernel(float* __restrict__ pe) {
    int idx = blockIdx.x * blockDim.x + threadIdx.x;
    if (idx >= LPE * DMODEL) return;
    int l  = idx >> 10;
    int kk = idx & 1023;
    int p2 = kk & ~1;
    float expnt = (float)p2 / 1024.0f;
    float denom = powf(10000.0f, expnt);
    float t = (float)(l - 1022);
    float ang = t / denom;
    float v = (kk & 1) ? cosf(ang) : sinf(ang);
    pe[idx] = v * 0.03125f;
}

// ===========================================================================
// TF32 mma.sync GEMM (unchanged from R3, passing at 4.5e-4)
// ===========================================================================
#define ASTR 36
#define BSTR 136
#define A_STAGE (128 * ASTR)
#define B_STAGE (32 * BSTR)
#define GEMM_SMEM_BYTES ((2 * A_STAGE + 2 * B_STAGE) * 4)

__global__ __launch_bounds__(256)
void gemm_mma_kernel(const float* __restrict__ A, const float* __restrict__ B,
                     float* __restrict__ C, int M, int N, int K) {
    extern __shared__ float sm[];
    float* AsBase = sm;
    float* BsBase = sm + 2 * A_STAGE;

    int tid  = threadIdx.x;
    int wid  = tid >> 5;
    int lane = tid & 31;
    int g    = lane >> 2;
    int tg   = lane & 3;
    int wm0  = (wid >> 2) * 64;
    int wn0  = (wid & 3) * 32;
    int bm = blockIdx.y * 128;
    int bn = blockIdx.x * 128;

    float acc[4][4][4];
#pragma unroll
    for (int mt = 0; mt < 4; mt++)
#pragma unroll
        for (int nt = 0; nt < 4; nt++)
#pragma unroll
            for (int r = 0; r < 4; r++) acc[mt][nt][r] = 0.0f;

    float4 pa[4], pb[4];

    auto ldTile = [&](int k0) {
#pragma unroll
        for (int it = 0; it < 4; it++) {
            int l = tid + 256 * it;
            int row = l >> 3, c4 = (l & 7) << 2;
            int gr = bm + row;
            pa[it] = (gr < M)
                ? *(const float4*)(A + (size_t)gr * K + k0 + c4)
                : make_float4(0.f, 0.f, 0.f, 0.f);
        }
#pragma unroll
        for (int it = 0; it < 4; it++) {
            int l = tid + 256 * it;
            int kr = l >> 5, n4 = (l & 31) << 2;
            pb[it] = *(const float4*)(B + (size_t)(k0 + kr) * N + bn + n4);
        }
    };

    auto stsTile = [&](int s) {
        float* as = AsBase + s * A_STAGE;
        float* bs = BsBase + s * B_STAGE;
#pragma unroll
        for (int it = 0; it < 4; it++) {
            int l = tid + 256 * it;
            int row = l >> 3, c4 = (l & 7) << 2;
            uint4 v = make_uint4(f2tf32(pa[it].x), f2tf32(pa[it].y),
                                 f2tf32(pa[it].z), f2tf32(pa[it].w));
            *(uint4*)(as + row * ASTR + c4) = v;
        }
#pragma unroll
        for (int it = 0; it < 4; it++) {
            int l = tid + 256 * it;
            int kr = l >> 5, n4 = (l & 31) << 2;
            uint4 v = make_uint4(f2tf32(pb[it].x), f2tf32(pb[it].y),
                                 f2tf32(pb[it].z), f2tf32(pb[it].w));
            *(uint4*)(bs + kr * BSTR + n4) = v;
        }
    };

    auto compute = [&](int s) {
        const float* as = AsBase + s * A_STAGE;
        const float* bs = BsBase + s * B_STAGE;
#pragma unroll
        for (int ks = 0; ks < 4; ks++) {
            int k8 = ks * 8;
            uint32_t af[4][4], bf[4][2];
#pragma unroll
            for (int mt = 0; mt < 4; mt++) {
                const float* p = as + (wm0 + mt * 16 + g) * ASTR + k8 + tg;
                af[mt][0] = __float_as_uint(p[0]);
                af[mt][1] = __float_as_uint(p[8 * ASTR]);
                af[mt][2] = __float_as_uint(p[4]);
                af[mt][3] = __float_as_uint(p[8 * ASTR + 4]);
            }
#pragma unroll
            for (int nt = 0; nt < 4; nt++) {
                const float* p = bs + (k8 + tg) * BSTR + wn0 + nt * 8 + g;
                bf[nt][0] = __float_as_uint(p[0]);
                bf[nt][1] = __float_as_uint(p[4 * BSTR]);
            }
#pragma unroll
            for (int mt = 0; mt < 4; mt++)
#pragma unroll
                for (int nt = 0; nt < 4; nt++)
                    mma_tf32(acc[mt][nt], af[mt], bf[nt]);
        }
    };

    int T = K >> 5;
    ldTile(0);
    stsTile(0);
    __syncthreads();

    for (int t = 0; t < T; t++) {
        int s = t & 1;
        if (t + 1 < T) ldTile((t + 1) << 5);
        compute(s);
        if (t + 1 < T) {
            stsTile(s ^ 1);
            __syncthreads();
        }
    }

#pragma unroll
    for (int mt = 0; mt < 4; mt++) {
        int r0 = bm + wm0 + mt * 16 + g;
        int r1 = r0 + 8;
#pragma unroll
        for (int nt = 0; nt < 4; nt++) {
            int col = bn + wn0 + nt * 8 + 2 * tg;
            if (r0 < M)
                *(float2*)(C + (size_t)r0 * N + col) =
                    make_float2(acc[mt][nt][0], acc[mt][nt][1]);
            if (r1 < M)
                *(float2*)(C + (size_t)r1 * N + col) =
                    make_float2(acc[mt][nt][2], acc[mt][nt][3]);
        }
    }
}

// ===========================================================================
// Tensor-core fused relative attention.
// CTA: 64 q-rows, 4 warps (16 rows each), 128 threads, 2 CTAs/SM.
// Smem (floats): Ks[64x64sw]=4096, Vs[64x64sw]=4096, PEl[128x64sw]=8192,
//                U (union: Qstage 2x4096 / Spos 64x136 / Pbuf 64x64sw)=8704,
//                Msk=64.  Total 25152 floats = 100608 B.
// ===========================================================================
#define AT_KS 0
#define AT_VS 4096
#define AT_PE 8192
#define AT_U  16384
#define AT_MSK 25088
#define AT_SMEM_BYTES (25152 * 4)
#define SPSTR 136

__global__ __launch_bounds__(128, 2)
void attn_mma_kernel(const float* __restrict__ qkv, const float* __restrict__ pek,
                     const unsigned char* __restrict__ mask,
                     const float* __restrict__ cb, const float* __restrict__ pb,
                     float* __restrict__ ao) {
    extern __shared__ float sm[];
    float* Ks  = sm + AT_KS;
    float* Vs  = sm + AT_VS;
    float* PEl = sm + AT_PE;
    float* U   = sm + AT_U;
    float* Msk = sm + AT_MSK;

    int tid = threadIdx.x;
    int wid = tid >> 5;
    int lane = tid & 31;
    int g = lane >> 2;
    int tg = lane & 3;
    int qt = blockIdx.x & 15;
    int bh = blockIdx.x >> 4;
    int h  = bh & 15;
    int b  = bh >> 4;
    int q0 = qt * 64;
    int wrow = wid * 16;

    const float* cbh = cb + h * DHEAD;
    const float* pbh = pb + h * DHEAD;

    // ---- Stage Q (content + pos) into U, swizzled tf32 ----
    float* Qc = U;
    float* Qp = U + 4096;
    for (int idx = tid; idx < 1024; idx += 128) {
        int i = idx >> 4, cc = idx & 15;
        int c4 = cc * 4;
        const float* src = qkv + ((size_t)(b * SEQ + q0 + i)) * 3072 + h * 192 + c4;
        float4 v = *(const float4*)src;
        int sa = i * 64 + (((cc ^ (i & 7)) << 2));
        bool z = (q0 + i == 0);
        Qc[sa + 0] = f2tf32f(v.x + cbh[c4 + 0]);
        Qc[sa + 1] = f2tf32f(v.y + cbh[c4 + 1]);
        Qc[sa + 2] = f2tf32f(v.z + cbh[c4 + 2]);
        Qc[sa + 3] = f2tf32f(v.w + cbh[c4 + 3]);
        Qp[sa + 0] = z ? 0.0f : f2tf32f(v.x + pbh[c4 + 0]);
        Qp[sa + 1] = z ? 0.0f : f2tf32f(v.y + pbh[c4 + 1]);
        Qp[sa + 2] = z ? 0.0f : f2tf32f(v.z + pbh[c4 + 2]);
        Qp[sa + 3] = z ? 0.0f : f2tf32f(v.w + pbh[c4 + 3]);
    }
    __syncthreads();

    // ---- Load Q fragments into registers (persist across k-tiles) ----
    uint32_t qcf[8][4], qpf[8][4];
    int r0l = wrow + g, r1l = wrow + g + 8;
#pragma unroll
    for (int ks = 0; ks < 8; ks++) {
        int c0 = ks * 8 + tg, c1 = c0 + 4;
        qcf[ks][0] = __float_as_uint(Qc[swz(r0l, c0)]);
        qcf[ks][1] = __float_as_uint(Qc[swz(r1l, c0)]);
        qcf[ks][2] = __float_as_uint(Qc[swz(r0l, c1)]);
        qcf[ks][3] = __float_as_uint(Qc[swz(r1l, c1)]);
        qpf[ks][0] = __float_as_uint(Qp[swz(r0l, c0)]);
        qpf[ks][1] = __float_as_uint(Qp[swz(r1l, c0)]);
        qpf[ks][2] = __float_as_uint(Qp[swz(r0l, c1)]);
        qpf[ks][3] = __float_as_uint(Qp[swz(r1l, c1)]);
    }

    float oac[8][4];
#pragma unroll
    for (int nt = 0; nt < 8; nt++)
#pragma unroll
        for (int r = 0; r < 4; r++) oac[nt][r] = 0.0f;
    float m0 = -1e30f, m1 = -1e30f, l0 = 0.0f, l1 = 0.0f;

    int nt0 = 6 - 2 * wid;   // band n-tile origin for this warp

    for (int kt = 0; kt < 16; kt++) {
        int k0 = kt * 64;
        int lbase = 959 + k0 - q0;
        __syncthreads();   // prev iter reads done; Q frag loads done (iter 0)

        // ---- Stage K, V ----
        for (int idx = tid; idx < 1024; idx += 128) {
            int i = idx >> 4, cc = idx & 15;
            const float* base = qkv + ((size_t)(b * SEQ + k0 + i)) * 3072 + h * 192;
            float4 kv = *(const float4*)(base + 64 + cc * 4);
            float4 vv = *(const float4*)(base + 128 + cc * 4);
            int sa = i * 64 + (((cc ^ (i & 7)) << 2));
            Ks[sa + 0] = f2tf32f(kv.x); Ks[sa + 1] = f2tf32f(kv.y);
            Ks[sa + 2] = f2tf32f(kv.z); Ks[sa + 3] = f2tf32f(kv.w);
            Vs[sa + 0] = f2tf32f(vv.x); Vs[sa + 1] = f2tf32f(vv.y);
            Vs[sa + 2] = f2tf32f(vv.z); Vs[sa + 3] = f2tf32f(vv.w);
        }
        // ---- Stage PE band (128 rows) ----
        for (int idx = tid; idx < 2048; idx += 128) {
            int l = idx >> 4, cc = idx & 15;
            int lg = lbase + l;
            float4 v = (lg >= 0 && lg < LPE)
                ? *(const float4*)(pek + (size_t)lg * DMODEL + h * DHEAD + cc * 4)
                : make_float4(0.f, 0.f, 0.f, 0.f);
            int sa = l * 64 + (((cc ^ (l & 7)) << 2));
            PEl[sa + 0] = f2tf32f(v.x); PEl[sa + 1] = f2tf32f(v.y);
            PEl[sa + 2] = f2tf32f(v.z); PEl[sa + 3] = f2tf32f(v.w);
        }
        if (tid < 64) Msk[tid] = mask[b * SEQ + k0 + tid] ? -1e30f : 0.0f;
        __syncthreads();

        // ---- Spos = Qp @ PEband^T (only the 10 n-tiles this warp gathers) ----
        float* Spos = U;
#pragma unroll
        for (int t = 0; t < 10; t++) {
            int n0 = (nt0 + t) * 8;
            float sp[4] = {0.f, 0.f, 0.f, 0.f};
#pragma unroll
            for (int ks = 0; ks < 8; ks++) {
                uint32_t bf[2];
                bf[0] = __float_as_uint(PEl[swz(n0 + g, ks * 8 + tg)]);
                bf[1] = __float_as_uint(PEl[swz(n0 + g, ks * 8 + tg + 4)]);
                mma_tf32(sp, qpf[ks], bf);
            }
            Spos[r0l * SPSTR + n0 + 2 * tg]     = sp[0];
            Spos[r0l * SPSTR + n0 + 2 * tg + 1] = sp[1];
            Spos[r1l * SPSTR + n0 + 2 * tg]     = sp[2];
            Spos[r1l * SPSTR + n0 + 2 * tg + 1] = sp[3];
        }

        // ---- S_c = Qc @ K^T ----
        float sc[8][4];
#pragma unroll
        for (int nt = 0; nt < 8; nt++) {
            int n0 = nt * 8;
            sc[nt][0] = sc[nt][1] = sc[nt][2] = sc[nt][3] = 0.0f;
#pragma unroll
            for (int ks = 0; ks < 8; ks++) {
                uint32_t bf[2];
                bf[0] = __float_as_uint(Ks[swz(n0 + g, ks * 8 + tg)]);
                bf[1] = __float_as_uint(Ks[swz(n0 + g, ks * 8 + tg + 4)]);
                mma_tf32(sc[nt], qcf[ks], bf);
            }
        }
        __syncwarp();   // Spos cross-lane visibility within warp

        // ---- Gather band + combine + mask + row max ----
        float mt0 = -1e30f, mt1 = -1e30f;
#pragma unroll
        for (int nt = 0; nt < 8; nt++) {
            int j0 = nt * 8 + 2 * tg;
            float p0 = Spos[r0l * SPSTR + (j0 - r0l + 63)];
            float p1 = Spos[r0l * SPSTR + (j0 + 1 - r0l + 63)];
            float p2 = Spos[r1l * SPSTR + (j0 - r1l + 63)];
            float p3 = Spos[r1l * SPSTR + (j0 + 1 - r1l + 63)];
            if (kt == 0 && j0 == 0) { p0 = 0.0f; p2 = 0.0f; }  // key 0: no pos
            float mk0 = Msk[j0], mk1 = Msk[j0 + 1];
            sc[nt][0] = (sc[nt][0] + p0) * 0.125f + mk0;
            sc[nt][1] = (sc[nt][1] + p1) * 0.125f + mk1;
            sc[nt][2] = (sc[nt][2] + p2) * 0.125f + mk0;
            sc[nt][3] = (sc[nt][3] + p3) * 0.125f + mk1;
            mt0 = fmaxf(mt0, fmaxf(sc[nt][0], sc[nt][1]));
            mt1 = fmaxf(mt1, fmaxf(sc[nt][2], sc[nt][3]));
        }
        mt0 = fmaxf(mt0, __shfl_xor_sync(0xffffffffu, mt0, 1));
        mt0 = fmaxf(mt0, __shfl_xor_sync(0xffffffffu, mt0, 2));
        mt1 = fmaxf(mt1, __shfl_xor_sync(0xffffffffu, mt1, 1));
        mt1 = fmaxf(mt1, __shfl_xor_sync(0xffffffffu, mt1, 2));

        // ---- Online softmax ----
        float mn0 = fmaxf(m0, mt0), mn1 = fmaxf(m1, mt1);
        float c0 = __expf(m0 - mn0), c1 = __expf(m1 - mn1);
        m0 = mn0; m1 = mn1;
#pragma unroll
        for (int nt = 0; nt < 8; nt++) {
            oac[nt][0] *= c0; oac[nt][1] *= c0;
            oac[nt][2] *= c1; oac[nt][3] *= c1;
        }
        float rs0 = 0.0f, rs1 = 0.0f;
#pragma unroll
        for (int nt = 0; nt < 8; nt++) {
            sc[nt][0] = __expf(sc[nt][0] - mn0);
            sc[nt][1] = __expf(sc[nt][1] - mn0);
            sc[nt][2] = __expf(sc[nt][2] - mn1);
            sc[nt][3] = __expf(sc[nt][3] - mn1);
            rs0 += sc[nt][0] + sc[nt][1];
            rs1 += sc[nt][2] + sc[nt][3];
        }
        rs0 += __shfl_xor_sync(0xffffffffu, rs0, 1);
        rs0 += __shfl_xor_sync(0xffffffffu, rs0, 2);
        rs1 += __shfl_xor_sync(0xffffffffu, rs1, 1);
        rs1 += __shfl_xor_sync(0xffffffffu, rs1, 2);
        l0 = l0 * c0 + rs0;
        l1 = l1 * c1 + rs1;

        __syncthreads();   // all gathers done before Pbuf overwrites U

        // ---- Write P (tf32) ----
        float* Pbuf = U;
#pragma unroll
        for (int nt = 0; nt < 8; nt++) {
            int j0 = nt * 8 + 2 * tg;
            Pbuf[swz(r0l, j0)]     = f2tf32f(sc[nt][0]);
            Pbuf[swz(r0l, j0 + 1)] = f2tf32f(sc[nt][1]);
            Pbuf[swz(r1l, j0)]     = f2tf32f(sc[nt][2]);
            Pbuf[swz(r1l, j0 + 1)] = f2tf32f(sc[nt][3]);
        }
        __syncwarp();

        // ---- O += P @ V ----
        uint32_t pf[8][4];
#pragma unroll
        for (int ks = 0; ks < 8; ks++) {
            int cc0 = ks * 8 + tg, cc1 = cc0 + 4;
            pf[ks][0] = __float_as_uint(Pbuf[swz(r0l, cc0)]);
            pf[ks][1] = __float_as_uint(Pbuf[swz(r1l, cc0)]);
            pf[ks][2] = __float_as_uint(Pbuf[swz(r0l, cc1)]);
            pf[ks][3] = __float_as_uint(Pbuf[swz(r1l, cc1)]);
        }
#pragma unroll
        for (int nt = 0; nt < 8; nt++) {
            int n0 = nt * 8;
#pragma unroll
            for (int ks = 0; ks < 8; ks++) {
                uint32_t bf[2];
                bf[0] = __float_as_uint(Vs[swz(ks * 8 + tg, n0 + g)]);
                bf[1] = __float_as_uint(Vs[swz(ks * 8 + tg + 4, n0 + g)]);
                mma_tf32(oac[nt], pf[ks], bf);
            }
        }
    }

    // ---- Epilogue ----
    float inv0 = 1.0f / l0, inv1 = 1.0f / l1;
    size_t rowA = ((size_t)(b * SEQ + q0 + r0l)) * DMODEL + h * DHEAD;
    size_t rowB = ((size_t)(b * SEQ + q0 + r1l)) * DMODEL + h * DHEAD;
#pragma unroll
    for (int nt = 0; nt < 8; nt++) {
        int col = nt * 8 + 2 * tg;
        *(float2*)(ao + rowA + col) = make_float2(oac[nt][0] * inv0, oac[nt][1] * inv0);
        *(float2*)(ao + rowB + col) = make_float2(oac[nt][2] * inv1, oac[nt][3] * inv1);
    }
}

// ---------------------------------------------------------------------------
extern "C" void kernel_launch(void* const* d_in, const int* in_sizes, int n_in,
                              void* d_out, int out_size) {
    const float* x          = (const float*)d_in[0];
    const unsigned char* mk = (const unsigned char*)d_in[1];
    const float* Wqkv       = (const float*)d_in[2];
    const float* Wpe        = (const float*)d_in[3];
    const float* Wo         = (const float*)d_in[4];
    const float* cb         = (const float*)d_in[5];
    const float* pb         = (const float*)d_in[6];
    float* out              = (float*)d_out;

    float *qkv, *pe, *pek, *ao;
    cudaGetSymbolAddress((void**)&qkv, g_qkv);
    cudaGetSymbolAddress((void**)&pe,  g_pe);
    cudaGetSymbolAddress((void**)&pek, g_pek);
    cudaGetSymbolAddress((void**)&ao,  g_ao);

    cudaFuncSetAttribute(gemm_mma_kernel,
                         cudaFuncAttributeMaxDynamicSharedMemorySize,
                         GEMM_SMEM_BYTES);
    cudaFuncSetAttribute(attn_mma_kernel,
                         cudaFuncAttributeMaxDynamicSharedMemorySize,
                         AT_SMEM_BYTES);

    pegen_kernel<<<(LPE * DMODEL + 255) / 256, 256>>>(pe);

    {
        dim3 grid(3072 / 128, 4096 / 128);
        gemm_mma_kernel<<<grid, 256, GEMM_SMEM_BYTES>>>(x, Wqkv, qkv,
                                                        BSZ * SEQ, 3 * DMODEL, DMODEL);
    }
    {
        dim3 grid(1024 / 128, (LPE + 127) / 128);
        gemm_mma_kernel<<<grid, 256, GEMM_SMEM_BYTES>>>(pe, Wpe, pek,
                                                        LPE, DMODEL, DMODEL);
    }

    attn_mma_kernel<<<BSZ * NHEAD * (SEQ / 64), 128, AT_SMEM_BYTES>>>(
        qkv, pek, mk, cb, pb, ao);

    {
        dim3 grid(1024 / 128, 4096 / 128);
        gemm_mma_kernel<<<grid, 256, GEMM_SMEM_BYTES>>>(ao, Wo, out,
                                                        BSZ * SEQ, DMODEL, DMODEL);
    }
}

// round 5
// speedup vs baseline: 3.0977x; 1.0010x over previous
#include <cuda_runtime.h>
#include <cuda_bf16.h>
#include <cstdint>
#include <math.h>

// Problem constants
#define BSZ 4
#define SEQ 1024
#define DMODEL 1024
#define NHEAD 16
#define DHEAD 64
#define LPE 2045   // 2*s-1, s = 1023

// Scratch
__device__ float g_qkv[BSZ * SEQ * 3 * DMODEL];
__device__ float g_pe [LPE * DMODEL];
__device__ float g_pek[LPE * DMODEL];
__device__ float g_ao [BSZ * SEQ * DMODEL];

// ---------------------------------------------------------------------------
__device__ __forceinline__ uint32_t f2tf32(float x) {
    uint32_t y;
    asm("cvt.rna.tf32.f32 %0, %1;" : "=r"(y) : "f"(x));
    return y;
}
__device__ __forceinline__ float f2tf32f(float x) {
    return __uint_as_float(f2tf32(x));
}

__device__ __forceinline__ void mma_tf32(float* d, const uint32_t* a,
                                         const uint32_t* b) {
    asm volatile(
        "mma.sync.aligned.m16n8k8.row.col.f32.tf32.tf32.f32 "
        "{%0,%1,%2,%3}, {%4,%5,%6,%7}, {%8,%9}, {%0,%1,%2,%3};\n"
        : "+f"(d[0]), "+f"(d[1]), "+f"(d[2]), "+f"(d[3])
        : "r"(a[0]), "r"(a[1]), "r"(a[2]), "r"(a[3]),
          "r"(b[0]), "r"(b[1]));
}

// XOR-swizzled 64-float row layout: conflict-free frag loads + optimal STS.128
__device__ __forceinline__ int swz(int row, int col) {
    return row * 64 + ((((col >> 2) ^ (row & 7)) << 2) | (col & 3));
}

// ---------------------------------------------------------------------------
__global__ void pegen_kernel(float* __restrict__ pe) {
    int idx = blockIdx.x * blockDim.x + threadIdx.x;
    if (idx >= LPE * DMODEL) return;
    int l  = idx >> 10;
    int kk = idx & 1023;
    int p2 = kk & ~1;
    float expnt = (float)p2 / 1024.0f;
    float denom = powf(10000.0f, expnt);
    float t = (float)(l - 1022);
    float ang = t / denom;
    float v = (kk & 1) ? cosf(ang) : sinf(ang);
    pe[idx] = v * 0.03125f;
}

// ===========================================================================
// TF32 mma.sync GEMM (unchanged from R3, passing at 4.5e-4)
// ===========================================================================
#define ASTR 36
#define BSTR 136
#define A_STAGE (128 * ASTR)
#define B_STAGE (32 * BSTR)
#define GEMM_SMEM_BYTES ((2 * A_STAGE + 2 * B_STAGE) * 4)

__global__ __launch_bounds__(256)
void gemm_mma_kernel(const float* __restrict__ A, const float* __restrict__ B,
                     float* __restrict__ C, int M, int N, int K) {
    extern __shared__ float sm[];
    float* AsBase = sm;
    float* BsBase = sm + 2 * A_STAGE;

    int tid  = threadIdx.x;
    int wid  = tid >> 5;
    int lane = tid & 31;
    int g    = lane >> 2;
    int tg   = lane & 3;
    int wm0  = (wid >> 2) * 64;
    int wn0  = (wid & 3) * 32;
    int bm = blockIdx.y * 128;
    int bn = blockIdx.x * 128;

    float acc[4][4][4];
#pragma unroll
    for (int mt = 0; mt < 4; mt++)
#pragma unroll
        for (int nt = 0; nt < 4; nt++)
#pragma unroll
            for (int r = 0; r < 4; r++) acc[mt][nt][r] = 0.0f;

    float4 pa[4], pb[4];

    auto ldTile = [&](int k0) {
#pragma unroll
        for (int it = 0; it < 4; it++) {
            int l = tid + 256 * it;
            int row = l >> 3, c4 = (l & 7) << 2;
            int gr = bm + row;
            pa[it] = (gr < M)
                ? *(const float4*)(A + (size_t)gr * K + k0 + c4)
                : make_float4(0.f, 0.f, 0.f, 0.f);
        }
#pragma unroll
        for (int it = 0; it < 4; it++) {
            int l = tid + 256 * it;
            int kr = l >> 5, n4 = (l & 31) << 2;
            pb[it] = *(const float4*)(B + (size_t)(k0 + kr) * N + bn + n4);
        }
    };

    auto stsTile = [&](int s) {
        float* as = AsBase + s * A_STAGE;
        float* bs = BsBase + s * B_STAGE;
#pragma unroll
        for (int it = 0; it < 4; it++) {
            int l = tid + 256 * it;
            int row = l >> 3, c4 = (l & 7) << 2;
            uint4 v = make_uint4(f2tf32(pa[it].x), f2tf32(pa[it].y),
                                 f2tf32(pa[it].z), f2tf32(pa[it].w));
            *(uint4*)(as + row * ASTR + c4) = v;
        }
#pragma unroll
        for (int it = 0; it < 4; it++) {
            int l = tid + 256 * it;
            int kr = l >> 5, n4 = (l & 31) << 2;
            uint4 v = make_uint4(f2tf32(pb[it].x), f2tf32(pb[it].y),
                                 f2tf32(pb[it].z), f2tf32(pb[it].w));
            *(uint4*)(bs + kr * BSTR + n4) = v;
        }
    };

    auto compute = [&](int s) {
        const float* as = AsBase + s * A_STAGE;
        const float* bs = BsBase + s * B_STAGE;
#pragma unroll
        for (int ks = 0; ks < 4; ks++) {
            int k8 = ks * 8;
            uint32_t af[4][4], bf[4][2];
#pragma unroll
            for (int mt = 0; mt < 4; mt++) {
                const float* p = as + (wm0 + mt * 16 + g) * ASTR + k8 + tg;
                af[mt][0] = __float_as_uint(p[0]);
                af[mt][1] = __float_as_uint(p[8 * ASTR]);
                af[mt][2] = __float_as_uint(p[4]);
                af[mt][3] = __float_as_uint(p[8 * ASTR + 4]);
            }
#pragma unroll
            for (int nt = 0; nt < 4; nt++) {
                const float* p = bs + (k8 + tg) * BSTR + wn0 + nt * 8 + g;
                bf[nt][0] = __float_as_uint(p[0]);
                bf[nt][1] = __float_as_uint(p[4 * BSTR]);
            }
#pragma unroll
            for (int mt = 0; mt < 4; mt++)
#pragma unroll
                for (int nt = 0; nt < 4; nt++)
                    mma_tf32(acc[mt][nt], af[mt], bf[nt]);
        }
    };

    int T = K >> 5;
    ldTile(0);
    stsTile(0);
    __syncthreads();

    for (int t = 0; t < T; t++) {
        int s = t & 1;
        if (t + 1 < T) ldTile((t + 1) << 5);
        compute(s);
        if (t + 1 < T) {
            stsTile(s ^ 1);
            __syncthreads();
        }
    }

#pragma unroll
    for (int mt = 0; mt < 4; mt++) {
        int r0 = bm + wm0 + mt * 16 + g;
        int r1 = r0 + 8;
#pragma unroll
        for (int nt = 0; nt < 4; nt++) {
            int col = bn + wn0 + nt * 8 + 2 * tg;
            if (r0 < M)
                *(float2*)(C + (size_t)r0 * N + col) =
                    make_float2(acc[mt][nt][0], acc[mt][nt][1]);
            if (r1 < M)
                *(float2*)(C + (size_t)r1 * N + col) =
                    make_float2(acc[mt][nt][2], acc[mt][nt][3]);
        }
    }
}

// ===========================================================================
// Tensor-core fused relative attention.
// CTA: 64 q-rows, 4 warps (16 rows each), 128 threads, 2 CTAs/SM.
// Smem (floats): Ks[64x64sw]=4096, Vs[64x64sw]=4096, PEl[128x64sw]=8192,
//                U (union: Qstage 2x4096 / Spos 64x136 / Pbuf 64x64sw)=8704,
//                Msk=64.  Total 25152 floats = 100608 B.
// ===========================================================================
#define AT_KS 0
#define AT_VS 4096
#define AT_PE 8192
#define AT_U  16384
#define AT_MSK 25088
#define AT_SMEM_BYTES (25152 * 4)
#define SPSTR 136

__global__ __launch_bounds__(128, 2)
void attn_mma_kernel(const float* __restrict__ qkv, const float* __restrict__ pek,
                     const unsigned char* __restrict__ mask,
                     const float* __restrict__ cb, const float* __restrict__ pb,
                     float* __restrict__ ao) {
    extern __shared__ float sm[];
    float* Ks  = sm + AT_KS;
    float* Vs  = sm + AT_VS;
    float* PEl = sm + AT_PE;
    float* U   = sm + AT_U;
    float* Msk = sm + AT_MSK;

    int tid = threadIdx.x;
    int wid = tid >> 5;
    int lane = tid & 31;
    int g = lane >> 2;
    int tg = lane & 3;
    int qt = blockIdx.x & 15;
    int bh = blockIdx.x >> 4;
    int h  = bh & 15;
    int b  = bh >> 4;
    int q0 = qt * 64;
    int wrow = wid * 16;

    const float* cbh = cb + h * DHEAD;
    const float* pbh = pb + h * DHEAD;

    // ---- Stage Q (content + pos) into U, swizzled tf32 ----
    float* Qc = U;
    float* Qp = U + 4096;
    for (int idx = tid; idx < 1024; idx += 128) {
        int i = idx >> 4, cc = idx & 15;
        int c4 = cc * 4;
        const float* src = qkv + ((size_t)(b * SEQ + q0 + i)) * 3072 + h * 192 + c4;
        float4 v = *(const float4*)src;
        int sa = i * 64 + (((cc ^ (i & 7)) << 2));
        bool z = (q0 + i == 0);
        Qc[sa + 0] = f2tf32f(v.x + cbh[c4 + 0]);
        Qc[sa + 1] = f2tf32f(v.y + cbh[c4 + 1]);
        Qc[sa + 2] = f2tf32f(v.z + cbh[c4 + 2]);
        Qc[sa + 3] = f2tf32f(v.w + cbh[c4 + 3]);
        Qp[sa + 0] = z ? 0.0f : f2tf32f(v.x + pbh[c4 + 0]);
        Qp[sa + 1] = z ? 0.0f : f2tf32f(v.y + pbh[c4 + 1]);
        Qp[sa + 2] = z ? 0.0f : f2tf32f(v.z + pbh[c4 + 2]);
        Qp[sa + 3] = z ? 0.0f : f2tf32f(v.w + pbh[c4 + 3]);
    }
    __syncthreads();

    // ---- Load Q fragments into registers (persist across k-tiles) ----
    uint32_t qcf[8][4], qpf[8][4];
    int r0l = wrow + g, r1l = wrow + g + 8;
#pragma unroll
    for (int ks = 0; ks < 8; ks++) {
        int c0 = ks * 8 + tg, c1 = c0 + 4;
        qcf[ks][0] = __float_as_uint(Qc[swz(r0l, c0)]);
        qcf[ks][1] = __float_as_uint(Qc[swz(r1l, c0)]);
        qcf[ks][2] = __float_as_uint(Qc[swz(r0l, c1)]);
        qcf[ks][3] = __float_as_uint(Qc[swz(r1l, c1)]);
        qpf[ks][0] = __float_as_uint(Qp[swz(r0l, c0)]);
        qpf[ks][1] = __float_as_uint(Qp[swz(r1l, c0)]);
        qpf[ks][2] = __float_as_uint(Qp[swz(r0l, c1)]);
        qpf[ks][3] = __float_as_uint(Qp[swz(r1l, c1)]);
    }

    float oac[8][4];
#pragma unroll
    for (int nt = 0; nt < 8; nt++)
#pragma unroll
        for (int r = 0; r < 4; r++) oac[nt][r] = 0.0f;
    float m0 = -1e30f, m1 = -1e30f, l0 = 0.0f, l1 = 0.0f;

    int nt0 = 6 - 2 * wid;   // band n-tile origin for this warp

    for (int kt = 0; kt < 16; kt++) {
        int k0 = kt * 64;
        int lbase = 959 + k0 - q0;
        __syncthreads();   // prev iter reads done; Q frag loads done (iter 0)

        // ---- Stage K, V ----
        for (int idx = tid; idx < 1024; idx += 128) {
            int i = idx >> 4, cc = idx & 15;
            const float* base = qkv + ((size_t)(b * SEQ + k0 + i)) * 3072 + h * 192;
            float4 kv = *(const float4*)(base + 64 + cc * 4);
            float4 vv = *(const float4*)(base + 128 + cc * 4);
            int sa = i * 64 + (((cc ^ (i & 7)) << 2));
            Ks[sa + 0] = f2tf32f(kv.x); Ks[sa + 1] = f2tf32f(kv.y);
            Ks[sa + 2] = f2tf32f(kv.z); Ks[sa + 3] = f2tf32f(kv.w);
            Vs[sa + 0] = f2tf32f(vv.x); Vs[sa + 1] = f2tf32f(vv.y);
            Vs[sa + 2] = f2tf32f(vv.z); Vs[sa + 3] = f2tf32f(vv.w);
        }
        // ---- Stage PE band (128 rows) ----
        for (int idx = tid; idx < 2048; idx += 128) {
            int l = idx >> 4, cc = idx & 15;
            int lg = lbase + l;
            float4 v = (lg >= 0 && lg < LPE)
                ? *(const float4*)(pek + (size_t)lg * DMODEL + h * DHEAD + cc * 4)
                : make_float4(0.f, 0.f, 0.f, 0.f);
            int sa = l * 64 + (((cc ^ (l & 7)) << 2));
            PEl[sa + 0] = f2tf32f(v.x); PEl[sa + 1] = f2tf32f(v.y);
            PEl[sa + 2] = f2tf32f(v.z); PEl[sa + 3] = f2tf32f(v.w);
        }
        if (tid < 64) Msk[tid] = mask[b * SEQ + k0 + tid] ? -1e30f : 0.0f;
        __syncthreads();

        // ---- Spos = Qp @ PEband^T (only the 10 n-tiles this warp gathers) ----
        float* Spos = U;
#pragma unroll
        for (int t = 0; t < 10; t++) {
            int n0 = (nt0 + t) * 8;
            float sp[4] = {0.f, 0.f, 0.f, 0.f};
#pragma unroll
            for (int ks = 0; ks < 8; ks++) {
                uint32_t bf[2];
                bf[0] = __float_as_uint(PEl[swz(n0 + g, ks * 8 + tg)]);
                bf[1] = __float_as_uint(PEl[swz(n0 + g, ks * 8 + tg + 4)]);
                mma_tf32(sp, qpf[ks], bf);
            }
            Spos[r0l * SPSTR + n0 + 2 * tg]     = sp[0];
            Spos[r0l * SPSTR + n0 + 2 * tg + 1] = sp[1];
            Spos[r1l * SPSTR + n0 + 2 * tg]     = sp[2];
            Spos[r1l * SPSTR + n0 + 2 * tg + 1] = sp[3];
        }

        // ---- S_c = Qc @ K^T ----
        float sc[8][4];
#pragma unroll
        for (int nt = 0; nt < 8; nt++) {
            int n0 = nt * 8;
            sc[nt][0] = sc[nt][1] = sc[nt][2] = sc[nt][3] = 0.0f;
#pragma unroll
            for (int ks = 0; ks < 8; ks++) {
                uint32_t bf[2];
                bf[0] = __float_as_uint(Ks[swz(n0 + g, ks * 8 + tg)]);
                bf[1] = __float_as_uint(Ks[swz(n0 + g, ks * 8 + tg + 4)]);
                mma_tf32(sc[nt], qcf[ks], bf);
            }
        }
        __syncwarp();   // Spos cross-lane visibility within warp

        // ---- Gather band + combine + mask + row max ----
        float mt0 = -1e30f, mt1 = -1e30f;
#pragma unroll
        for (int nt = 0; nt < 8; nt++) {
            int j0 = nt * 8 + 2 * tg;
            float p0 = Spos[r0l * SPSTR + (j0 - r0l + 63)];
            float p1 = Spos[r0l * SPSTR + (j0 + 1 - r0l + 63)];
            float p2 = Spos[r1l * SPSTR + (j0 - r1l + 63)];
            float p3 = Spos[r1l * SPSTR + (j0 + 1 - r1l + 63)];
            if (kt == 0 && j0 == 0) { p0 = 0.0f; p2 = 0.0f; }  // key 0: no pos
            float mk0 = Msk[j0], mk1 = Msk[j0 + 1];
            sc[nt][0] = (sc[nt][0] + p0) * 0.125f + mk0;
            sc[nt][1] = (sc[nt][1] + p1) * 0.125f + mk1;
            sc[nt][2] = (sc[nt][2] + p2) * 0.125f + mk0;
            sc[nt][3] = (sc[nt][3] + p3) * 0.125f + mk1;
            mt0 = fmaxf(mt0, fmaxf(sc[nt][0], sc[nt][1]));
            mt1 = fmaxf(mt1, fmaxf(sc[nt][2], sc[nt][3]));
        }
        mt0 = fmaxf(mt0, __shfl_xor_sync(0xffffffffu, mt0, 1));
        mt0 = fmaxf(mt0, __shfl_xor_sync(0xffffffffu, mt0, 2));
        mt1 = fmaxf(mt1, __shfl_xor_sync(0xffffffffu, mt1, 1));
        mt1 = fmaxf(mt1, __shfl_xor_sync(0xffffffffu, mt1, 2));

        // ---- Online softmax ----
        float mn0 = fmaxf(m0, mt0), mn1 = fmaxf(m1, mt1);
        float c0 = __expf(m0 - mn0), c1 = __expf(m1 - mn1);
        m0 = mn0; m1 = mn1;
#pragma unroll
        for (int nt = 0; nt < 8; nt++) {
            oac[nt][0] *= c0; oac[nt][1] *= c0;
            oac[nt][2] *= c1; oac[nt][3] *= c1;
        }
        float rs0 = 0.0f, rs1 = 0.0f;
#pragma unroll
        for (int nt = 0; nt < 8; nt++) {
            sc[nt][0] = __expf(sc[nt][0] - mn0);
            sc[nt][1] = __expf(sc[nt][1] - mn0);
            sc[nt][2] = __expf(sc[nt][2] - mn1);
            sc[nt][3] = __expf(sc[nt][3] - mn1);
            rs0 += sc[nt][0] + sc[nt][1];
            rs1 += sc[nt][2] + sc[nt][3];
        }
        rs0 += __shfl_xor_sync(0xffffffffu, rs0, 1);
        rs0 += __shfl_xor_sync(0xffffffffu, rs0, 2);
        rs1 += __shfl_xor_sync(0xffffffffu, rs1, 1);
        rs1 += __shfl_xor_sync(0xffffffffu, rs1, 2);
        l0 = l0 * c0 + rs0;
        l1 = l1 * c1 + rs1;

        __syncthreads();   // all gathers done before Pbuf overwrites U

        // ---- Write P (tf32) ----
        float* Pbuf = U;
#pragma unroll
        for (int nt = 0; nt < 8; nt++) {
            int j0 = nt * 8 + 2 * tg;
            Pbuf[swz(r0l, j0)]     = f2tf32f(sc[nt][0]);
            Pbuf[swz(r0l, j0 + 1)] = f2tf32f(sc[nt][1]);
            Pbuf[swz(r1l, j0)]     = f2tf32f(sc[nt][2]);
            Pbuf[swz(r1l, j0 + 1)] = f2tf32f(sc[nt][3]);
        }
        __syncwarp();

        // ---- O += P @ V ----
        uint32_t pf[8][4];
#pragma unroll
        for (int ks = 0; ks < 8; ks++) {
            int cc0 = ks * 8 + tg, cc1 = cc0 + 4;
            pf[ks][0] = __float_as_uint(Pbuf[swz(r0l, cc0)]);
            pf[ks][1] = __float_as_uint(Pbuf[swz(r1l, cc0)]);
            pf[ks][2] = __float_as_uint(Pbuf[swz(r0l, cc1)]);
            pf[ks][3] = __float_as_uint(Pbuf[swz(r1l, cc1)]);
        }
#pragma unroll
        for (int nt = 0; nt < 8; nt++) {
            int n0 = nt * 8;
#pragma unroll
            for (int ks = 0; ks < 8; ks++) {
                uint32_t bf[2];
                bf[0] = __float_as_uint(Vs[swz(ks * 8 + tg, n0 + g)]);
                bf[1] = __float_as_uint(Vs[swz(ks * 8 + tg + 4, n0 + g)]);
                mma_tf32(oac[nt], pf[ks], bf);
            }
        }
    }

    // ---- Epilogue ----
    float inv0 = 1.0f / l0, inv1 = 1.0f / l1;
    size_t rowA = ((size_t)(b * SEQ + q0 + r0l)) * DMODEL + h * DHEAD;
    size_t rowB = ((size_t)(b * SEQ + q0 + r1l)) * DMODEL + h * DHEAD;
#pragma unroll
    for (int nt = 0; nt < 8; nt++) {
        int col = nt * 8 + 2 * tg;
        *(float2*)(ao + rowA + col) = make_float2(oac[nt][0] * inv0, oac[nt][1] * inv0);
        *(float2*)(ao + rowB + col) = make_float2(oac[nt][2] * inv1, oac[nt][3] * inv1);
    }
}

// ---------------------------------------------------------------------------
extern "C" void kernel_launch(void* const* d_in, const int* in_sizes, int n_in,
                              void* d_out, int out_size) {
    const float* x          = (const float*)d_in[0];
    const unsigned char* mk = (const unsigned char*)d_in[1];
    const float* Wqkv       = (const float*)d_in[2];
    const float* Wpe        = (const float*)d_in[3];
    const float* Wo         = (const float*)d_in[4];
    const float* cb         = (const float*)d_in[5];
    const float* pb         = (const float*)d_in[6];
    float* out              = (float*)d_out;

    float *qkv, *pe, *pek, *ao;
    cudaGetSymbolAddress((void**)&qkv, g_qkv);
    cudaGetSymbolAddress((void**)&pe,  g_pe);
    cudaGetSymbolAddress((void**)&pek, g_pek);
    cudaGetSymbolAddress((void**)&ao,  g_ao);

    cudaFuncSetAttribute(gemm_mma_kernel,
                         cudaFuncAttributeMaxDynamicSharedMemorySize,
                         GEMM_SMEM_BYTES);
    cudaFuncSetAttribute(attn_mma_kernel,
                         cudaFuncAttributeMaxDynamicSharedMemorySize,
                         AT_SMEM_BYTES);

    pegen_kernel<<<(LPE * DMODEL + 255) / 256, 256>>>(pe);

    {
        dim3 grid(3072 / 128, 4096 / 128);
        gemm_mma_kernel<<<grid, 256, GEMM_SMEM_BYTES>>>(x, Wqkv, qkv,
                                                        BSZ * SEQ, 3 * DMODEL, DMODEL);
    }
    {
        dim3 grid(1024 / 128, (LPE + 127) / 128);
        gemm_mma_kernel<<<grid, 256, GEMM_SMEM_BYTES>>>(pe, Wpe, pek,
                                                        LPE, DMODEL, DMODEL);
    }

    attn_mma_kernel<<<BSZ * NHEAD * (SEQ / 64), 128, AT_SMEM_BYTES>>>(
        qkv, pek, mk, cb, pb, ao);

    {
        dim3 grid(1024 / 128, 4096 / 128);
        gemm_mma_kernel<<<grid, 256, GEMM_SMEM_BYTES>>>(ao, Wo, out,
                                                        BSZ * SEQ, DMODEL, DMODEL);
    }
}